// round 1
// baseline (speedup 1.0000x reference)
#include <cuda_runtime.h>

#define NB 16
#define NRR 300
#define CC 150
#define NRL 50
#define DPRO 512
#define DROI 12544
#define DREL 256
#define KK 10
#define MAXREC 100
#define NT 2700   // 300 * 9

// Output layout (float elements), return order:
// so_pro_out (16,320,512), boxes_so_out (16,320,8), so_cls_out (16,320,300),
// rel_out (16,320,256), so_roi_out (16,320,12544), vis_out (16,300)
#define OFF_PRO 0
#define OFF_BOX 2621440
#define OFF_CLS 2662400
#define OFF_REL 4198400
#define OFF_ROI 5509120
#define OFF_VIS 69734400

__device__ int g_ent[NB * KK];

__device__ __forceinline__ float sigm(float x) { return 1.0f / (1.0f + expf(-x)); }

// ---------------------------------------------------------------------------
// Kernel 1: per-image selection. One block per image (16 blocks, 256 threads).
// Computes ent_idx (top-10 entity rows, sorted ascending) -> g_ent, and vis_out.
// ---------------------------------------------------------------------------
__global__ __launch_bounds__(256) void selector_kernel(
    const float* __restrict__ class_logits,     // (16,600,150)
    const float* __restrict__ pred_bboxes,      // (16,600,4)
    const float* __restrict__ so_class_logits,  // (16,300,300)
    const float* __restrict__ pred_bboxes_so,   // (16,300,8)
    const float* __restrict__ rel_logits,       // (16,300,50)
    const unsigned char* __restrict__ vis,      // (16,300)
    float* __restrict__ out_vis)                // -> out + OFF_VIS
{
    __shared__ float sh_triple[NT];
    __shared__ short sh_sc[NRR * 3], sh_oc[NRR * 3];
    __shared__ int   sh_selt[MAXREC];
    __shared__ int   sh_eq[128];
    __shared__ int   sh_cnt, sh_cnt_gt, sh_cnt_eq;
    __shared__ int   sel_class[2 * MAXREC];
    __shared__ float sel_box[2 * MAXREC * 4];
    __shared__ float sel_a2[2 * MAXREC];
    __shared__ float sh_score[NRR];
    __shared__ float rv[256];
    __shared__ int   ri[256];
    __shared__ int   sh_ent[KK];

    const int n = blockIdx.x;
    const int tid = threadIdx.x;

    // --- Phase 1: per-pair top-3 subject/object classes + triple scores ---
    for (int p = tid; p < NRR; p += 256) {
        const float* rl = rel_logits + (n * NRR + p) * NRL;
        float rm = rl[0];
        #pragma unroll 5
        for (int c = 1; c < NRL; c++) rm = fmaxf(rm, rl[c]);
        float relmax = sigm(rm);

        const float* sl = so_class_logits + (n * NRR + p) * (2 * CC);
        // subject top-3 over [0,150)
        float v0 = -1e30f, v1 = -1e30f, v2 = -1e30f; int i0 = 0, i1 = 0, i2 = 0;
        for (int c = 0; c < CC; c++) {
            float v = sl[c];
            if (v > v0)      { v2 = v1; i2 = i1; v1 = v0; i1 = i0; v0 = v; i0 = c; }
            else if (v > v1) { v2 = v1; i2 = i1; v1 = v;  i1 = c; }
            else if (v > v2) { v2 = v;  i2 = c; }
        }
        float ss0 = sigm(v0), ss1 = sigm(v1), ss2 = sigm(v2);
        sh_sc[p * 3 + 0] = (short)i0; sh_sc[p * 3 + 1] = (short)i1; sh_sc[p * 3 + 2] = (short)i2;
        // object top-3 over [150,300)
        float w0 = -1e30f, w1 = -1e30f, w2 = -1e30f; int j0 = 0, j1 = 0, j2 = 0;
        for (int c = 0; c < CC; c++) {
            float v = sl[CC + c];
            if (v > w0)      { w2 = w1; j2 = j1; w1 = w0; j1 = j0; w0 = v; j0 = c; }
            else if (v > w1) { w2 = w1; j2 = j1; w1 = v;  j1 = c; }
            else if (v > w2) { w2 = v;  j2 = c; }
        }
        float os0 = sigm(w0), os1 = sigm(w1), os2 = sigm(w2);
        sh_oc[p * 3 + 0] = (short)j0; sh_oc[p * 3 + 1] = (short)j1; sh_oc[p * 3 + 2] = (short)j2;

        float sarr[3] = {ss0, ss1, ss2};
        float oarr[3] = {os0, os1, os2};
        #pragma unroll
        for (int i = 0; i < 3; i++)
            #pragma unroll
            for (int j = 0; j < 3; j++)
                sh_triple[p * 9 + i * 3 + j] = (relmax * sarr[i]) * oarr[j];
    }
    __syncthreads();

    // --- Phase 2: top-100 of 2700 via binary search on float bits ---
    unsigned lo = 0u, hi = 0x3F800000u;  // values in (0,1)
    while (lo < hi) {
        unsigned mid = lo + ((hi - lo + 1u) >> 1);
        if (tid == 0) sh_cnt = 0;
        __syncthreads();
        int local = 0;
        for (int t = tid; t < NT; t += 256)
            local += (__float_as_uint(sh_triple[t]) >= mid) ? 1 : 0;
        atomicAdd(&sh_cnt, local);
        __syncthreads();
        if (sh_cnt >= MAXREC) lo = mid; else hi = mid - 1u;
        __syncthreads();
    }
    const unsigned thr = lo;

    if (tid == 0) { sh_cnt_gt = 0; sh_cnt_eq = 0; }
    __syncthreads();
    for (int t = tid; t < NT; t += 256) {
        unsigned b = __float_as_uint(sh_triple[t]);
        if (b > thr) {
            int p = atomicAdd(&sh_cnt_gt, 1);
            if (p < MAXREC) sh_selt[p] = t;
        } else if (b == thr) {
            int p = atomicAdd(&sh_cnt_eq, 1);
            if (p < 128) sh_eq[p] = t;
        }
    }
    __syncthreads();
    if (tid == 0) {
        int c1 = sh_cnt_gt; if (c1 > MAXREC) c1 = MAXREC;
        int need = MAXREC - c1;
        int ne = sh_cnt_eq; if (ne > 128) ne = 128;
        for (int a = 1; a < ne; a++) {  // sort ties ascending (lowest index wins)
            int key = sh_eq[a]; int b = a - 1;
            while (b >= 0 && sh_eq[b] > key) { sh_eq[b + 1] = sh_eq[b]; b--; }
            sh_eq[b + 1] = key;
        }
        for (int a = 0; a < need && a < ne; a++) sh_selt[c1 + a] = sh_eq[a];
    }
    __syncthreads();

    // Build selected (class, box, area) pairs: 200 entries (subject, object interleaved)
    for (int m = tid; m < MAXREC; m += 256) {
        int t = sh_selt[m];
        int p = t / 9, r2 = t % 9, si = r2 / 3, oj = r2 % 3;
        const float* b = pred_bboxes_so + (n * NRR + p) * 8;
        sel_class[2 * m]     = sh_sc[p * 3 + si];
        sel_class[2 * m + 1] = sh_oc[p * 3 + oj];
        #pragma unroll
        for (int c = 0; c < 4; c++) {
            sel_box[(2 * m) * 4 + c]     = b[c];
            sel_box[(2 * m + 1) * 4 + c] = b[4 + c];
        }
        sel_a2[2 * m]     = (b[3] - b[1] + 1.f) * (b[2] - b[0] + 1.f);
        sel_a2[2 * m + 1] = (b[7] - b[5] + 1.f) * (b[6] - b[4] + 1.f);
    }
    __syncthreads();

    // --- Phase 3: per-entity scores ---
    for (int s = tid; s < NRR; s += 256) {
        const float* cl = class_logits + (n * 2 * NRR + 2 * s) * CC;
        float mv = cl[0]; int mi = 0;
        for (int c = 1; c < CC; c++) { float v = cl[c]; if (v > mv) { mv = v; mi = c; } }
        const float* bp = pred_bboxes + (n * 2 * NRR + 2 * s) * 4;
        float x1 = bp[0], y1 = bp[1], x2 = bp[2], y2 = bp[3];
        float a1 = (y2 - y1 + 1.f) * (x2 - x1 + 1.f);
        bool hit = false;
        for (int m = 0; m < 2 * MAXREC; m++) {
            if (sel_class[m] != mi) continue;
            float lx = fmaxf(x1, sel_box[m * 4 + 0]);
            float ly = fmaxf(y1, sel_box[m * 4 + 1]);
            float rx = fminf(x2, sel_box[m * 4 + 2]);
            float ry = fminf(y2, sel_box[m * 4 + 3]);
            float w = fmaxf(rx - lx, 0.f), h = fmaxf(ry - ly, 0.f);
            float inter = w * h;
            float iou = inter / (a1 + sel_a2[m] - inter);
            if (iou >= 0.5f) { hit = true; break; }
        }
        float sc = sigm(mv) - (hit ? 2.f : 0.f) - (vis[n * NRR + s] ? 2.f : 0.f);
        sh_score[s] = sc;
    }
    __syncthreads();

    // --- Phase 4: top-10 entities (iterative argmax, tie -> smallest index) ---
    for (int k = 0; k < KK; k++) {
        float bv = -1e30f; int bi = 0x7fffffff;
        for (int s = tid; s < NRR; s += 256) {
            float v = sh_score[s];
            if (v > bv || (v == bv && s < bi)) { bv = v; bi = s; }
        }
        rv[tid] = bv; ri[tid] = bi;
        __syncthreads();
        for (int stp = 128; stp > 0; stp >>= 1) {
            if (tid < stp) {
                if (rv[tid + stp] > rv[tid] ||
                    (rv[tid + stp] == rv[tid] && ri[tid + stp] < ri[tid])) {
                    rv[tid] = rv[tid + stp]; ri[tid] = ri[tid + stp];
                }
            }
            __syncthreads();
        }
        if (tid == 0) { sh_ent[k] = ri[0]; sh_score[ri[0]] = -1e30f; }
        __syncthreads();
    }
    if (tid == 0) {
        for (int a = 1; a < KK; a++) {  // sort ascending
            int key = sh_ent[a]; int b = a - 1;
            while (b >= 0 && sh_ent[b] > key) { sh_ent[b + 1] = sh_ent[b]; b--; }
            sh_ent[b + 1] = key;
        }
        for (int a = 0; a < KK; a++) g_ent[n * KK + a] = sh_ent[a];
    }
    __syncthreads();

    // vis_out
    for (int s = tid; s < NRR; s += 256) {
        bool sel = false;
        #pragma unroll
        for (int a = 0; a < KK; a++) sel |= (sh_ent[a] == s);
        out_vis[n * NRR + s] = (vis[n * NRR + s] || sel) ? 1.0f : 0.0f;
    }
}

// ---------------------------------------------------------------------------
// Kernel 2: bulk float4 copy of the 300 "main" rows of all 5 outputs.
// Pure memcpy with row-stride remap (300 -> 320 rows). Independent of selection.
// ---------------------------------------------------------------------------
#define S_PRO4 (NB * NRR * 128u)    //  614400
#define S_BOX4 (NB * NRR * 2u)      //    9600
#define S_CLS4 (NB * NRR * 75u)     //  360000
#define S_REL4 (NB * NRR * 64u)     //  307200
#define S_ROI4 (NB * NRR * 3136u)   // 15052800
#define TOT4   (S_PRO4 + S_BOX4 + S_CLS4 + S_REL4 + S_ROI4)  // 16344000

__device__ __forceinline__ void copy_region(const float4* __restrict__ src,
                                            float4* __restrict__ out,
                                            unsigned r, unsigned D4, unsigned off4)
{
    unsigned n = r / (NRR * D4);
    unsigned rem = r - n * (NRR * D4);
    unsigned row = rem / D4;
    unsigned col = rem - row * D4;
    out[off4 + (n * 320u + row) * D4 + col] = src[r];
}

__global__ __launch_bounds__(256) void main_copy_kernel(
    const float4* __restrict__ so_pro,
    const float4* __restrict__ boxes_so,
    const float4* __restrict__ so_cls,
    const float4* __restrict__ rel_feat,
    const float4* __restrict__ so_roi,
    float4* __restrict__ out)
{
    unsigned i = blockIdx.x * 256u + threadIdx.x;
    if (i < S_PRO4) { copy_region(so_pro, out, i, 128u, OFF_PRO / 4u); return; }
    i -= S_PRO4;
    if (i < S_BOX4) { copy_region(boxes_so, out, i, 2u, OFF_BOX / 4u); return; }
    i -= S_BOX4;
    if (i < S_CLS4) { copy_region(so_cls, out, i, 75u, OFF_CLS / 4u); return; }
    i -= S_CLS4;
    if (i < S_REL4) { copy_region(rel_feat, out, i, 64u, OFF_REL / 4u); return; }
    i -= S_REL4;
    if (i < S_ROI4) { copy_region(so_roi, out, i, 3136u, OFF_ROI / 4u); return; }
}

// ---------------------------------------------------------------------------
// Kernel 3: gather of the 20 aux rows (rows 300..319) per output. Scalar loads
// (half-swap of a 300-wide row breaks float4 alignment); only ~17 MB traffic.
// ---------------------------------------------------------------------------
#define A_PRO (NB * 20u * 512u)
#define A_BOX (NB * 20u * 8u)
#define A_CLS (NB * 20u * 300u)
#define A_REL (NB * 20u * 256u)
#define A_ROI (NB * 20u * 12544u)
#define TOTA  (A_PRO + A_BOX + A_CLS + A_REL + A_ROI)   // 4358400

__global__ __launch_bounds__(256) void aux_copy_kernel(
    const float* __restrict__ pro_features,   // (16,300,512)
    const float* __restrict__ pred_bboxes,    // (16,600,4) == (16,300,8)
    const float* __restrict__ class_logits,   // (16,600,150) == (16,300,300)
    const float* __restrict__ aux_rel,        // (16,300,512)
    const float* __restrict__ roi_features,   // (16,300,12544)
    float* __restrict__ out)
{
    unsigned i = blockIdx.x * 256u + threadIdx.x;

    if (i < A_PRO) {
        unsigned n = i / (20u * 512u), rem = i % (20u * 512u);
        unsigned j = rem / 512u, col = rem % 512u;
        int e = g_ent[n * KK + (j % 10u)];
        unsigned col2 = (j < 10u) ? col : ((col + 256u) & 511u);
        out[OFF_PRO + (n * 320u + 300u + j) * 512u + col] =
            pro_features[(n * 300u + e) * 512u + col2];
        return;
    }
    i -= A_PRO;
    if (i < A_BOX) {
        unsigned n = i / (20u * 8u), rem = i % (20u * 8u);
        unsigned j = rem / 8u, col = rem % 8u;
        int e = g_ent[n * KK + (j % 10u)];
        unsigned col2 = (j < 10u) ? col : ((col + 4u) & 7u);
        out[OFF_BOX + (n * 320u + 300u + j) * 8u + col] =
            pred_bboxes[n * 2400u + (unsigned)e * 8u + col2];
        return;
    }
    i -= A_BOX;
    if (i < A_CLS) {
        unsigned n = i / (20u * 300u), rem = i % (20u * 300u);
        unsigned j = rem / 300u, col = rem % 300u;
        int e = g_ent[n * KK + (j % 10u)];
        unsigned col2 = (j < 10u) ? col : (col < 150u ? col + 150u : col - 150u);
        out[OFF_CLS + (n * 320u + 300u + j) * 300u + col] =
            class_logits[n * 90000u + (unsigned)e * 300u + col2];
        return;
    }
    i -= A_CLS;
    if (i < A_REL) {
        unsigned n = i / (20u * 256u), rem = i % (20u * 256u);
        unsigned j = rem / 256u, col = rem % 256u;
        int e = g_ent[n * KK + (j % 10u)];
        unsigned col2 = col + ((j < 10u) ? 0u : 256u);
        out[OFF_REL + (n * 320u + 300u + j) * 256u + col] =
            aux_rel[(n * 300u + e) * 512u + col2];
        return;
    }
    i -= A_REL;
    if (i < A_ROI) {
        unsigned n = i / (20u * 12544u), rem = i % (20u * 12544u);
        unsigned j = rem / 12544u, col = rem % 12544u;
        int e = g_ent[n * KK + (j % 10u)];
        unsigned col2 = (j < 10u) ? col : (col < 6272u ? col + 6272u : col - 6272u);
        out[OFF_ROI + (n * 320u + 300u + j) * 12544u + col] =
            roi_features[(n * 300u + (unsigned)e) * 12544u + col2];
        return;
    }
}

// ---------------------------------------------------------------------------
extern "C" void kernel_launch(void* const* d_in, const int* in_sizes, int n_in,
                              void* d_out, int out_size)
{
    const float* aux_rel         = (const float*)d_in[0];   // (16,300,512)
    const float* class_logits    = (const float*)d_in[1];   // (16,600,150)
    const float* pred_bboxes     = (const float*)d_in[2];   // (16,600,4)
    const float* pro_features    = (const float*)d_in[3];   // (16,300,512)
    const float* roi_features    = (const float*)d_in[4];   // (16,300,12544)
    const float* so_class_logits = (const float*)d_in[5];   // (16,300,300)
    const float* pred_bboxes_so  = (const float*)d_in[6];   // (16,300,8)
    const float* so_pro          = (const float*)d_in[7];   // (16,300,512)
    const float* so_roi          = (const float*)d_in[8];   // (16,300,12544)
    const float* rel_logits      = (const float*)d_in[9];   // (16,300,50)
    const float* rel_feat        = (const float*)d_in[10];  // (16,300,256)
    const unsigned char* vis     = (const unsigned char*)d_in[11];  // (16,300)

    float* out = (float*)d_out;

    selector_kernel<<<NB, 256>>>(class_logits, pred_bboxes, so_class_logits,
                                 pred_bboxes_so, rel_logits, vis, out + OFF_VIS);

    main_copy_kernel<<<(TOT4 + 255u) / 256u, 256>>>(
        (const float4*)so_pro, (const float4*)pred_bboxes_so,
        (const float4*)so_class_logits, (const float4*)rel_feat,
        (const float4*)so_roi, (float4*)out);

    aux_copy_kernel<<<(TOTA + 255u) / 256u, 256>>>(
        pro_features, pred_bboxes, class_logits, aux_rel, roi_features, out);
}

// round 3
// speedup vs baseline: 2.4396x; 2.4396x over previous
#include <cuda_runtime.h>

#define NB 16
#define NRR 300
#define CC 150
#define NRL 50
#define KK 10
#define MAXREC 100
#define NT 2700   // 300 * 9
#define NEG_INF (-3.0e38f)
#define FULLM 0xFFFFFFFFu

// Output layout (float elements), return order:
// so_pro_out (16,320,512), boxes_so_out (16,320,8), so_cls_out (16,320,300),
// rel_out (16,320,256), so_roi_out (16,320,12544), vis_out (16,300)
#define OFF_PRO 0
#define OFF_BOX 2621440
#define OFF_CLS 2662400
#define OFF_REL 4198400
#define OFF_ROI 5509120
#define OFF_VIS 69734400

__device__ int   g_ent[NB * KK];
__device__ float g_triple[NB * NT];
__device__ int   g_sc[NB * NRR * 3];
__device__ int   g_oc[NB * NRR * 3];
__device__ int   g_mi[NB * NRR];
__device__ float g_pure[NB * NRR];

__device__ __forceinline__ float sigm(float x) { return 1.0f / (1.0f + expf(-x)); }

__device__ __forceinline__ void better(float nv, int ni, float& bv, int& bi) {
    if (nv > bv || (nv == bv && ni < bi)) { bv = nv; bi = ni; }
}

// warp argmax (value desc, index asc), result broadcast to all lanes
__device__ __forceinline__ void warp_argmax(float& bv, int& bi) {
    #pragma unroll
    for (int off = 16; off > 0; off >>= 1) {
        float ov = __shfl_down_sync(FULLM, bv, off);
        int   oi = __shfl_down_sync(FULLM, bi, off);
        better(ov, oi, bv, bi);
    }
    bv = __shfl_sync(FULLM, bv, 0);
    bi = __shfl_sync(FULLM, bi, 0);
}

// ---------------------------------------------------------------------------
// K1: one warp per task. Tasks 0..4799: pair (n,p) -> triple scores + top3
// classes. Tasks 4800..9599: entity (n,s) -> class argmax + sigmoid score.
// ---------------------------------------------------------------------------
__global__ __launch_bounds__(256) void k1_pairs_entities(
    const float* __restrict__ so_class_logits,  // (16,300,300)
    const float* __restrict__ rel_logits,       // (16,300,50)
    const float* __restrict__ class_logits)     // (16,600,150)
{
    const int w    = blockIdx.x * 8 + (threadIdx.x >> 5);
    const int lane = threadIdx.x & 31;

    if (w < NB * NRR) {
        // ---- pair task ----
        const int n = w / NRR, p = w % NRR;
        const float* sl = so_class_logits + (n * NRR + p) * (2 * CC);
        const float* rl = rel_logits + (n * NRR + p) * NRL;

        // load subject[0..150) and object[150..300), 5 slots each per lane
        float sv[5], ov[5]; int sidx[5];
        #pragma unroll
        for (int k = 0; k < 5; k++) {
            int c = lane + 32 * k;
            bool ok = (c < CC);
            sidx[k] = ok ? c : (1 << 30);
            sv[k] = ok ? sl[c] : NEG_INF;
            ov[k] = ok ? sl[CC + c] : NEG_INF;
        }
        // rel max
        float r = (lane < NRL) ? rl[lane] : NEG_INF;
        if (lane + 32 < NRL) r = fmaxf(r, rl[lane + 32]);
        #pragma unroll
        for (int off = 16; off > 0; off >>= 1)
            r = fmaxf(r, __shfl_xor_sync(FULLM, r, off));
        float relm = sigm(r);

        // top-3 subject
        float stv[3]; int sti[3];
        #pragma unroll
        for (int rnd = 0; rnd < 3; rnd++) {
            float bv = NEG_INF; int bi = (1 << 30);
            #pragma unroll
            for (int k = 0; k < 5; k++) better(sv[k], sidx[k], bv, bi);
            warp_argmax(bv, bi);
            stv[rnd] = bv; sti[rnd] = bi;
            #pragma unroll
            for (int k = 0; k < 5; k++) if (sidx[k] == bi) sv[k] = NEG_INF;
        }
        // top-3 object
        float otv[3]; int oti[3];
        #pragma unroll
        for (int rnd = 0; rnd < 3; rnd++) {
            float bv = NEG_INF; int bi = (1 << 30);
            #pragma unroll
            for (int k = 0; k < 5; k++) better(ov[k], sidx[k], bv, bi);
            warp_argmax(bv, bi);
            otv[rnd] = bv; oti[rnd] = bi;
            #pragma unroll
            for (int k = 0; k < 5; k++) if (sidx[k] == bi) ov[k] = NEG_INF;
        }

        float ss0 = sigm(stv[0]), ss1 = sigm(stv[1]), ss2 = sigm(stv[2]);
        float os0 = sigm(otv[0]), os1 = sigm(otv[1]), os2 = sigm(otv[2]);

        if (lane < 9) {
            int i = lane / 3, j = lane % 3;
            float ssv = (i == 0) ? ss0 : (i == 1) ? ss1 : ss2;
            float oov = (j == 0) ? os0 : (j == 1) ? os1 : os2;
            g_triple[n * NT + p * 9 + lane] = (relm * ssv) * oov;
        }
        if (lane < 3) {
            g_sc[(n * NRR + p) * 3 + lane] = sti[lane];
            g_oc[(n * NRR + p) * 3 + lane] = oti[lane];
        }
    } else if (w < 2 * NB * NRR) {
        // ---- entity task: argmax over class_logits row ----
        const int q = w - NB * NRR;
        const int n = q / NRR, s = q % NRR;
        const float* cl = class_logits + (n * 2 * NRR + 2 * s) * CC;
        float bv = NEG_INF; int bi = (1 << 30);
        #pragma unroll
        for (int k = 0; k < 5; k++) {
            int c = lane + 32 * k;
            if (c < CC) better(cl[c], c, bv, bi);
        }
        warp_argmax(bv, bi);
        if (lane == 0) {
            g_mi[n * NRR + s]   = bi;
            g_pure[n * NRR + s] = sigm(bv);
        }
    }
}

// ---------------------------------------------------------------------------
// K2: per image (16 blocks x 1024). Top-100 triples, IoU dedup, top-10
// entities, vis_out.
// ---------------------------------------------------------------------------
__global__ __launch_bounds__(1024) void k2_select(
    const float* __restrict__ pred_bboxes,     // (16,600,4)
    const float* __restrict__ pred_bboxes_so,  // (16,300,8)
    const unsigned char* __restrict__ vis,     // (16,300)
    float* __restrict__ out_vis)
{
    __shared__ float sh_triple[NT];
    __shared__ int   sh_selt[MAXREC];
    __shared__ int   sh_eq[128];
    __shared__ int   sh_cnt, sh_cnt_gt, sh_cnt_eq;
    __shared__ int   sel_class[2 * MAXREC];
    __shared__ float sel_box[2 * MAXREC * 4];
    __shared__ float sel_a2[2 * MAXREC];
    __shared__ float sh_score[NRR];
    __shared__ unsigned char sh_sel[NRR];
    __shared__ int   sh_ent[KK];
    __shared__ unsigned long long sh_key;

    const int n = blockIdx.x;
    const int tid = threadIdx.x;
    const int wid = tid >> 5;
    const int lane = tid & 31;

    for (int t = tid; t < NT; t += 1024) sh_triple[t] = g_triple[n * NT + t];
    if (tid < NRR) sh_sel[tid] = 0;
    __syncthreads();

    // --- top-100 threshold via binary search on float bits (values in (0,1)) ---
    unsigned lo = 0u, hi = 0x3F800000u;
    while (lo < hi) {
        unsigned mid = lo + ((hi - lo + 1u) >> 1);
        if (tid == 0) sh_cnt = 0;
        __syncthreads();
        int local = 0;
        for (int t = tid; t < NT; t += 1024)
            local += (__float_as_uint(sh_triple[t]) >= mid) ? 1 : 0;
        #pragma unroll
        for (int off = 16; off > 0; off >>= 1)
            local += __shfl_xor_sync(FULLM, local, off);
        if (lane == 0 && local) atomicAdd(&sh_cnt, local);
        __syncthreads();
        if (sh_cnt >= MAXREC) lo = mid; else hi = mid - 1u;
        __syncthreads();
    }
    const unsigned thr = lo;

    if (tid == 0) { sh_cnt_gt = 0; sh_cnt_eq = 0; }
    __syncthreads();
    for (int t = tid; t < NT; t += 1024) {
        unsigned b = __float_as_uint(sh_triple[t]);
        if (b > thr) {
            int p = atomicAdd(&sh_cnt_gt, 1);
            if (p < MAXREC) sh_selt[p] = t;
        } else if (b == thr) {
            int p = atomicAdd(&sh_cnt_eq, 1);
            if (p < 128) sh_eq[p] = t;
        }
    }
    __syncthreads();
    if (tid == 0) {
        int c1 = sh_cnt_gt; if (c1 > MAXREC) c1 = MAXREC;
        int need = MAXREC - c1;
        int ne = sh_cnt_eq; if (ne > 128) ne = 128;
        for (int a = 1; a < ne; a++) {   // ties: lowest index first
            int key = sh_eq[a]; int b = a - 1;
            while (b >= 0 && sh_eq[b] > key) { sh_eq[b + 1] = sh_eq[b]; b--; }
            sh_eq[b + 1] = key;
        }
        for (int a = 0; a < need && a < ne; a++) sh_selt[c1 + a] = sh_eq[a];
    }
    __syncthreads();

    // --- build selected (class, box, area): 200 entries ---
    if (tid < MAXREC) {
        int t = sh_selt[tid];
        int p = t / 9, r2 = t % 9, si = r2 / 3, oj = r2 % 3;
        const float* b = pred_bboxes_so + (n * NRR + p) * 8;
        sel_class[2 * tid]     = g_sc[(n * NRR + p) * 3 + si];
        sel_class[2 * tid + 1] = g_oc[(n * NRR + p) * 3 + oj];
        #pragma unroll
        for (int c = 0; c < 4; c++) {
            sel_box[(2 * tid) * 4 + c]     = b[c];
            sel_box[(2 * tid + 1) * 4 + c] = b[4 + c];
        }
        sel_a2[2 * tid]     = (b[3] - b[1] + 1.f) * (b[2] - b[0] + 1.f);
        sel_a2[2 * tid + 1] = (b[7] - b[5] + 1.f) * (b[6] - b[4] + 1.f);
    }
    __syncthreads();

    // --- entity scores: warp per entity, candidate loop over lanes ---
    for (int s = wid; s < NRR; s += 32) {
        int   mi   = g_mi[n * NRR + s];
        float pure = g_pure[n * NRR + s];
        const float* bp = pred_bboxes + (n * 2 * NRR + 2 * s) * 4;
        float x1 = bp[0], y1 = bp[1], x2 = bp[2], y2 = bp[3];
        float a1 = (y2 - y1 + 1.f) * (x2 - x1 + 1.f);
        bool fhit = false;
        for (int m = lane; m < 2 * MAXREC; m += 32) {
            if (sel_class[m] == mi) {
                float lx = fmaxf(x1, sel_box[m * 4 + 0]);
                float ly = fmaxf(y1, sel_box[m * 4 + 1]);
                float rx = fminf(x2, sel_box[m * 4 + 2]);
                float ry = fminf(y2, sel_box[m * 4 + 3]);
                float wdt = fmaxf(rx - lx, 0.f), hgt = fmaxf(ry - ly, 0.f);
                float inter = wdt * hgt;
                if (inter / (a1 + sel_a2[m] - inter) >= 0.5f) fhit = true;
            }
        }
        bool hit = __any_sync(FULLM, fhit);
        if (lane == 0)
            sh_score[s] = pure - (hit ? 2.f : 0.f)
                               - (vis[n * NRR + s] ? 2.f : 0.f);
    }
    __syncthreads();

    // --- top-10 entities via packed atomicMax (score desc, index asc) ---
    unsigned long long mykey = 0ull;
    if (tid < NRR) {
        float f = sh_score[tid];
        unsigned u = __float_as_uint(f);
        u ^= (u & 0x80000000u) ? 0xFFFFFFFFu : 0x80000000u;
        mykey = ((unsigned long long)u << 32) | (unsigned)(1023 - tid);
    }
    for (int k = 0; k < KK; k++) {
        if (tid == 0) sh_key = 0ull;
        __syncthreads();
        if (tid < NRR && !sh_sel[tid]) atomicMax(&sh_key, mykey);
        __syncthreads();
        if (tid == 0) {
            int s = 1023 - (int)(unsigned)(sh_key & 0xFFFFFFFFull);
            sh_ent[k] = s;
            sh_sel[s] = 1;
        }
        __syncthreads();
    }
    if (tid == 0) {
        for (int a = 1; a < KK; a++) {   // sort ascending
            int key = sh_ent[a]; int b = a - 1;
            while (b >= 0 && sh_ent[b] > key) { sh_ent[b + 1] = sh_ent[b]; b--; }
            sh_ent[b + 1] = key;
        }
        #pragma unroll
        for (int a = 0; a < KK; a++) g_ent[n * KK + a] = sh_ent[a];
    }
    __syncthreads();

    if (tid < NRR)
        out_vis[n * NRR + tid] = (vis[n * NRR + tid] || sh_sel[tid]) ? 1.0f : 0.0f;
}

// ---------------------------------------------------------------------------
// Kernel 2: bulk float4 copy of the 300 "main" rows of all 5 outputs.
// ---------------------------------------------------------------------------
#define S_PRO4 (NB * NRR * 128u)
#define S_BOX4 (NB * NRR * 2u)
#define S_CLS4 (NB * NRR * 75u)
#define S_REL4 (NB * NRR * 64u)
#define S_ROI4 (NB * NRR * 3136u)
#define TOT4   (S_PRO4 + S_BOX4 + S_CLS4 + S_REL4 + S_ROI4)  // 16344000

__device__ __forceinline__ void copy_region(const float4* __restrict__ src,
                                            float4* __restrict__ out,
                                            unsigned r, unsigned D4, unsigned off4)
{
    unsigned n = r / (NRR * D4);
    unsigned rem = r - n * (NRR * D4);
    unsigned row = rem / D4;
    unsigned col = rem - row * D4;
    out[off4 + (n * 320u + row) * D4 + col] = src[r];
}

__global__ __launch_bounds__(256) void main_copy_kernel(
    const float4* __restrict__ so_pro,
    const float4* __restrict__ boxes_so,
    const float4* __restrict__ so_cls,
    const float4* __restrict__ rel_feat,
    const float4* __restrict__ so_roi,
    float4* __restrict__ out)
{
    unsigned i = blockIdx.x * 256u + threadIdx.x;
    if (i < S_PRO4) { copy_region(so_pro, out, i, 128u, OFF_PRO / 4u); return; }
    i -= S_PRO4;
    if (i < S_BOX4) { copy_region(boxes_so, out, i, 2u, OFF_BOX / 4u); return; }
    i -= S_BOX4;
    if (i < S_CLS4) { copy_region(so_cls, out, i, 75u, OFF_CLS / 4u); return; }
    i -= S_CLS4;
    if (i < S_REL4) { copy_region(rel_feat, out, i, 64u, OFF_REL / 4u); return; }
    i -= S_REL4;
    if (i < S_ROI4) { copy_region(so_roi, out, i, 3136u, OFF_ROI / 4u); return; }
}

// ---------------------------------------------------------------------------
// Kernel 3: gather of the 20 aux rows (rows 300..319) per output.
// ---------------------------------------------------------------------------
#define A_PRO (NB * 20u * 512u)
#define A_BOX (NB * 20u * 8u)
#define A_CLS (NB * 20u * 300u)
#define A_REL (NB * 20u * 256u)
#define A_ROI (NB * 20u * 12544u)
#define TOTA  (A_PRO + A_BOX + A_CLS + A_REL + A_ROI)

__global__ __launch_bounds__(256) void aux_copy_kernel(
    const float* __restrict__ pro_features,
    const float* __restrict__ pred_bboxes,
    const float* __restrict__ class_logits,
    const float* __restrict__ aux_rel,
    const float* __restrict__ roi_features,
    float* __restrict__ out)
{
    unsigned i = blockIdx.x * 256u + threadIdx.x;

    if (i < A_PRO) {
        unsigned n = i / (20u * 512u), rem = i % (20u * 512u);
        unsigned j = rem / 512u, col = rem % 512u;
        int e = g_ent[n * KK + (j % 10u)];
        unsigned col2 = (j < 10u) ? col : ((col + 256u) & 511u);
        out[OFF_PRO + (n * 320u + 300u + j) * 512u + col] =
            pro_features[(n * 300u + e) * 512u + col2];
        return;
    }
    i -= A_PRO;
    if (i < A_BOX) {
        unsigned n = i / (20u * 8u), rem = i % (20u * 8u);
        unsigned j = rem / 8u, col = rem % 8u;
        int e = g_ent[n * KK + (j % 10u)];
        unsigned col2 = (j < 10u) ? col : ((col + 4u) & 7u);
        out[OFF_BOX + (n * 320u + 300u + j) * 8u + col] =
            pred_bboxes[n * 2400u + (unsigned)e * 8u + col2];
        return;
    }
    i -= A_BOX;
    if (i < A_CLS) {
        unsigned n = i / (20u * 300u), rem = i % (20u * 300u);
        unsigned j = rem / 300u, col = rem % 300u;
        int e = g_ent[n * KK + (j % 10u)];
        unsigned col2 = (j < 10u) ? col : (col < 150u ? col + 150u : col - 150u);
        out[OFF_CLS + (n * 320u + 300u + j) * 300u + col] =
            class_logits[n * 90000u + (unsigned)e * 300u + col2];
        return;
    }
    i -= A_CLS;
    if (i < A_REL) {
        unsigned n = i / (20u * 256u), rem = i % (20u * 256u);
        unsigned j = rem / 256u, col = rem % 256u;
        int e = g_ent[n * KK + (j % 10u)];
        unsigned col2 = col + ((j < 10u) ? 0u : 256u);
        out[OFF_REL + (n * 320u + 300u + j) * 256u + col] =
            aux_rel[(n * 300u + e) * 512u + col2];
        return;
    }
    i -= A_REL;
    if (i < A_ROI) {
        unsigned n = i / (20u * 12544u), rem = i % (20u * 12544u);
        unsigned j = rem / 12544u, col = rem % 12544u;
        int e = g_ent[n * KK + (j % 10u)];
        unsigned col2 = (j < 10u) ? col : (col < 6272u ? col + 6272u : col - 6272u);
        out[OFF_ROI + (n * 320u + 300u + j) * 12544u + col] =
            roi_features[(n * 300u + (unsigned)e) * 12544u + col2];
        return;
    }
}

// ---------------------------------------------------------------------------
extern "C" void kernel_launch(void* const* d_in, const int* in_sizes, int n_in,
                              void* d_out, int out_size)
{
    const float* aux_rel         = (const float*)d_in[0];
    const float* class_logits    = (const float*)d_in[1];
    const float* pred_bboxes     = (const float*)d_in[2];
    const float* pro_features    = (const float*)d_in[3];
    const float* roi_features    = (const float*)d_in[4];
    const float* so_class_logits = (const float*)d_in[5];
    const float* pred_bboxes_so  = (const float*)d_in[6];
    const float* so_pro          = (const float*)d_in[7];
    const float* so_roi          = (const float*)d_in[8];
    const float* rel_logits      = (const float*)d_in[9];
    const float* rel_feat        = (const float*)d_in[10];
    const unsigned char* vis     = (const unsigned char*)d_in[11];

    float* out = (float*)d_out;

    k1_pairs_entities<<<1200, 256>>>(so_class_logits, rel_logits, class_logits);

    k2_select<<<NB, 1024>>>(pred_bboxes, pred_bboxes_so, vis, out + OFF_VIS);

    main_copy_kernel<<<(TOT4 + 255u) / 256u, 256>>>(
        (const float4*)so_pro, (const float4*)pred_bboxes_so,
        (const float4*)so_class_logits, (const float4*)rel_feat,
        (const float4*)so_roi, (float4*)out);

    aux_copy_kernel<<<(TOTA + 255u) / 256u, 256>>>(
        pro_features, pred_bboxes, class_logits, aux_rel, roi_features, out);
}